// round 6
// baseline (speedup 1.0000x reference)
#include <cuda_runtime.h>

#define T_STEPS  1024
#define F_FEAT   2048
#define LATENT   128
#define ODE_H    256
#define GR       384          // 3*LATENT gate rows
#define G        16           // features per CTA
#define GP       8            // feature pairs per CTA
#define NGRP     4            // independent groups per CTA
#define GPG      2            // feature pairs per group
#define NTHREADS 512
#define NCTAS    (F_FEAT / G) // 128

typedef unsigned long long u64;

// ---------- packed f32x2 helpers ----------
__device__ __forceinline__ u64 ffma2(u64 a, u64 b, u64 c) {
    u64 d;
    asm("fma.rn.f32x2 %0, %1, %2, %3;" : "=l"(d) : "l"(a), "l"(b), "l"(c));
    return d;
}
__device__ __forceinline__ u64 dup2(float x) {
    u64 r;
    asm("mov.b64 %0, {%1, %1};" : "=l"(r) : "f"(x));
    return r;
}
__device__ __forceinline__ float2 unpk(u64 v) {
    float2 r;
    asm("mov.b64 {%0, %1}, %2;" : "=f"(r.x), "=f"(r.y) : "l"(v));
    return r;
}
__device__ __forceinline__ u64 pack2(float x, float y) {
    u64 r;
    asm("mov.b64 %0, {%1, %2};" : "=l"(r) : "f"(x), "f"(y));
    return r;
}
__device__ __forceinline__ u64 tanh2(u64 v) {
    const float2 f = unpk(v);
    return pack2(tanhf(f.x), tanhf(f.y));
}
__device__ __forceinline__ float fast_sigmoid(float x) {
    return __fdividef(1.0f, 1.0f + __expf(-x));
}
#define GBAR(id) asm volatile("bar.sync %0, 128;" :: "r"(id) : "memory")

// ---------- repacked (transposed) weights: coalesced mainloop loads ----------
__device__ float4 g_W1p[32 * 256];   // [k4*256 + j] = W1[j][4k4..]
__device__ float4 g_W2p[64 * 128];   // [k4*128 + j] = W2[j][4k4..]
__device__ float4 g_Whp[32 * 384];   // [k4*384 + j] = W_hh[j][4k4..]

__global__ void repack_kernel(const float* __restrict__ W1,
                              const float* __restrict__ W2,
                              const float* __restrict__ Whh)
{
    int i = blockIdx.x * blockDim.x + threadIdx.x;
    if (i < 32 * 256) {
        int k4 = i >> 8, j = i & 255;
        g_W1p[k4 * 256 + j] = *(const float4*)(W1 + j * LATENT + 4 * k4);
    } else if (i < 32 * 256 + 64 * 128) {
        int t = i - 32 * 256;
        int k4 = t >> 7, j = t & 127;
        g_W2p[k4 * 128 + j] = *(const float4*)(W2 + j * ODE_H + 4 * k4);
    } else if (i < 32 * 256 + 64 * 128 + 32 * 384) {
        int t = i - (32 * 256 + 64 * 128);
        int k4 = t / 384, j = t % 384;
        g_Whp[k4 * 384 + j] = *(const float4*)(Whh + j * LATENT + 4 * k4);
    }
}

// ---------- main persistent recurrence kernel ----------
__global__ __launch_bounds__(NTHREADS, 1)
void ode_rnn_kernel(const float* __restrict__ times,
                    const float* __restrict__ vals,
                    const float* __restrict__ mask,
                    const float* __restrict__ b1,
                    const float* __restrict__ b2,
                    const float* __restrict__ W_ih,
                    const float* __restrict__ b_ih,
                    const float* __restrict__ b_hh,
                    float* __restrict__ out)
{
    // 4 independent groups; each owns 2 feature-pairs
    __shared__ __align__(16) u64 hp[GP * LATENT];    // 8 KB  (group g: [g*256 .. ))
    __shared__ __align__(16) u64 pool[GP * GR];      // 24 KB (group g: [g*768 .. ))
    __shared__ float2 obs2[GP];
    __shared__ float2 m2[GP];

    const int tid = threadIdx.x;
    const int grp = tid >> 7;              // 0..3
    const int lt  = tid & 127;             // lane within group
    const int bar = grp + 1;               // named barrier id
    const int f0  = blockIdx.x * G;
    u64* __restrict__ hpg   = hp   + grp * GPG * LATENT;
    u64* __restrict__ poolg = pool + grp * GPG * GR;
    const int pb = grp * GPG;              // global pair base

    for (int idx = tid; idx < GP * LATENT; idx += NTHREADS)
        hp[idx] = 0ULL;
    __syncthreads();

    for (int i = 0; i < T_STEPS; ++i) {
        const int row = T_STEPS - 1 - i;               // reversed sequence
        float dt = 0.0f;
        if (i > 0) dt = __ldg(times + row + 1) - __ldg(times + row);

        if (lt < GPG) {
            obs2[pb + lt] = __ldg((const float2*)(vals + (long)row * F_FEAT + f0) + pb + lt);
            m2[pb + lt]   = __ldg((const float2*)(mask + (long)row * F_FEAT + f0) + pb + lt);
        }

        if (dt > 0.0f) {
            // ---- Phase 1: t1[p][j] = tanh(b1[j] + sum_k h2[p][k]*W1[j][k])
            //      JR=2 (rows lt, lt+128), 2 pairs ----
            {
                const int j0 = lt, j1 = lt + 128;
                u64 a0[GPG], a1[GPG];
                const u64 bj0 = dup2(__ldg(b1 + j0));
                const u64 bj1 = dup2(__ldg(b1 + j1));
                #pragma unroll
                for (int p = 0; p < GPG; ++p) { a0[p] = bj0; a1[p] = bj1; }
                #pragma unroll 4
                for (int k4 = 0; k4 < LATENT / 4; ++k4) {
                    const float4 wa = __ldg(g_W1p + k4 * ODE_H + j0);
                    const float4 wb = __ldg(g_W1p + k4 * ODE_H + j1);
                    const u64 wa0 = dup2(wa.x), wa1 = dup2(wa.y), wa2 = dup2(wa.z), wa3 = dup2(wa.w);
                    const u64 wb0 = dup2(wb.x), wb1 = dup2(wb.y), wb2 = dup2(wb.z), wb3 = dup2(wb.w);
                    #pragma unroll
                    for (int p = 0; p < GPG; ++p) {
                        const ulonglong2* hv = (const ulonglong2*)(hpg + p * LATENT);
                        const ulonglong2 x = hv[2 * k4];
                        const ulonglong2 y = hv[2 * k4 + 1];
                        a0[p] = ffma2(x.x, wa0, a0[p]); a1[p] = ffma2(x.x, wb0, a1[p]);
                        a0[p] = ffma2(x.y, wa1, a0[p]); a1[p] = ffma2(x.y, wb1, a1[p]);
                        a0[p] = ffma2(y.x, wa2, a0[p]); a1[p] = ffma2(y.x, wb2, a1[p]);
                        a0[p] = ffma2(y.y, wa3, a0[p]); a1[p] = ffma2(y.y, wb3, a1[p]);
                    }
                }
                #pragma unroll
                for (int p = 0; p < GPG; ++p) {
                    poolg[p * ODE_H + j0] = tanh2(a0[p]);
                    poolg[p * ODE_H + j1] = tanh2(a1[p]);
                }
            }
            GBAR(bar);

            // ---- Phase 2: h2[p][j] += dt * (b2[j] + sum_k t1[p][k]*W2[j][k])
            //      JR=1 (row lt), 2 pairs ----
            {
                const int j = lt;
                u64 acc[GPG];
                const u64 bj = dup2(__ldg(b2 + j));
                #pragma unroll
                for (int p = 0; p < GPG; ++p) acc[p] = bj;
                #pragma unroll 4
                for (int k4 = 0; k4 < ODE_H / 4; ++k4) {
                    const float4 w = __ldg(g_W2p + k4 * LATENT + j);
                    const u64 w0 = dup2(w.x), w1 = dup2(w.y), w2 = dup2(w.z), w3 = dup2(w.w);
                    #pragma unroll
                    for (int p = 0; p < GPG; ++p) {
                        const ulonglong2* tv = (const ulonglong2*)(poolg + p * ODE_H);
                        const ulonglong2 x = tv[2 * k4];
                        const ulonglong2 y = tv[2 * k4 + 1];
                        acc[p] = ffma2(x.x, w0, acc[p]);
                        acc[p] = ffma2(x.y, w1, acc[p]);
                        acc[p] = ffma2(y.x, w2, acc[p]);
                        acc[p] = ffma2(y.y, w3, acc[p]);
                    }
                }
                const u64 dt2 = dup2(dt);
                #pragma unroll
                for (int p = 0; p < GPG; ++p)
                    hpg[p * LATENT + j] = ffma2(acc[p], dt2, hpg[p * LATENT + j]);
            }
            GBAR(bar);
        }

        // ---- Phase 3: gh[p][j] = b_hh[j] + sum_k h2[p][k]*W_hh[j][k]
        //      JR=3 (rows lt, lt+128, lt+256), 2 pairs ----
        {
            const int j0 = lt, j1 = lt + 128, j2 = lt + 256;
            u64 a0[GPG], a1[GPG], a2[GPG];
            const u64 bj0 = dup2(__ldg(b_hh + j0));
            const u64 bj1 = dup2(__ldg(b_hh + j1));
            const u64 bj2 = dup2(__ldg(b_hh + j2));
            #pragma unroll
            for (int p = 0; p < GPG; ++p) { a0[p] = bj0; a1[p] = bj1; a2[p] = bj2; }
            #pragma unroll 4
            for (int k4 = 0; k4 < LATENT / 4; ++k4) {
                const float4 wa = __ldg(g_Whp + k4 * GR + j0);
                const float4 wb = __ldg(g_Whp + k4 * GR + j1);
                const float4 wc = __ldg(g_Whp + k4 * GR + j2);
                const u64 wa0 = dup2(wa.x), wa1 = dup2(wa.y), wa2 = dup2(wa.z), wa3 = dup2(wa.w);
                const u64 wb0 = dup2(wb.x), wb1 = dup2(wb.y), wb2 = dup2(wb.z), wb3 = dup2(wb.w);
                const u64 wc0 = dup2(wc.x), wc1 = dup2(wc.y), wc2 = dup2(wc.z), wc3 = dup2(wc.w);
                #pragma unroll
                for (int p = 0; p < GPG; ++p) {
                    const ulonglong2* hv = (const ulonglong2*)(hpg + p * LATENT);
                    const ulonglong2 x = hv[2 * k4];
                    const ulonglong2 y = hv[2 * k4 + 1];
                    a0[p] = ffma2(x.x, wa0, a0[p]); a1[p] = ffma2(x.x, wb0, a1[p]); a2[p] = ffma2(x.x, wc0, a2[p]);
                    a0[p] = ffma2(x.y, wa1, a0[p]); a1[p] = ffma2(x.y, wb1, a1[p]); a2[p] = ffma2(x.y, wc1, a2[p]);
                    a0[p] = ffma2(y.x, wa2, a0[p]); a1[p] = ffma2(y.x, wb2, a1[p]); a2[p] = ffma2(y.x, wc2, a2[p]);
                    a0[p] = ffma2(y.y, wa3, a0[p]); a1[p] = ffma2(y.y, wb3, a1[p]); a2[p] = ffma2(y.y, wc3, a2[p]);
                }
            }
            #pragma unroll
            for (int p = 0; p < GPG; ++p) {
                poolg[p * GR + j0] = a0[p];
                poolg[p * GR + j1] = a1[p];
                poolg[p * GR + j2] = a2[p];
            }
        }
        GBAR(bar);

        // ---- Update: GRU gates + mask mix (256 pair-elems per group) ----
        #pragma unroll
        for (int rep = 0; rep < (GPG * LATENT) / 128; ++rep) {
            const int idx = rep * 128 + lt;
            const int p = idx >> 7;               // local pair 0..1
            const int l = idx & (LATENT - 1);
            const float2 gr = unpk(poolg[p * GR + l]);
            const float2 gz = unpk(poolg[p * GR + LATENT + l]);
            const float2 gn = unpk(poolg[p * GR + 2 * LATENT + l]);
            const float2 ob = obs2[pb + p];
            const float2 mm = m2[pb + p];
            const float2 h  = unpk(hpg[p * LATENT + l]);
            const float wr = __ldg(W_ih + l);
            const float wz = __ldg(W_ih + LATENT + l);
            const float wn = __ldg(W_ih + 2 * LATENT + l);
            const float br = __ldg(b_ih + l);
            const float bz = __ldg(b_ih + LATENT + l);
            const float bn = __ldg(b_ih + 2 * LATENT + l);

            const float rX = fast_sigmoid(fmaf(ob.x, wr, br) + gr.x);
            const float zX = fast_sigmoid(fmaf(ob.x, wz, bz) + gz.x);
            const float nX = tanhf(fmaf(ob.x, wn, bn) + rX * gn.x);
            const float hcX = fmaf(zX, h.x - nX, nX);
            const float hX  = fmaf(mm.x, hcX - h.x, h.x);

            const float rY = fast_sigmoid(fmaf(ob.y, wr, br) + gr.y);
            const float zY = fast_sigmoid(fmaf(ob.y, wz, bz) + gz.y);
            const float nY = tanhf(fmaf(ob.y, wn, bn) + rY * gn.y);
            const float hcY = fmaf(zY, h.y - nY, nY);
            const float hY  = fmaf(mm.y, hcY - h.y, h.y);

            hpg[p * LATENT + l] = pack2(hX, hY);
        }
        GBAR(bar);
    }

    // write final h for this group's 2 pairs
    #pragma unroll
    for (int rep = 0; rep < (GPG * LATENT) / 128; ++rep) {
        const int idx = rep * 128 + lt;
        const int p = idx >> 7;
        const int l = idx & (LATENT - 1);
        const float2 v = unpk(hpg[p * LATENT + l]);
        out[(long)(f0 + 2 * (pb + p))     * LATENT + l] = v.x;
        out[(long)(f0 + 2 * (pb + p) + 1) * LATENT + l] = v.y;
    }
}

extern "C" void kernel_launch(void* const* d_in, const int* in_sizes, int n_in,
                              void* d_out, int out_size)
{
    (void)in_sizes; (void)n_in; (void)out_size;
    const float* times = (const float*)d_in[0];
    const float* vals  = (const float*)d_in[1];
    const float* mask  = (const float*)d_in[2];
    const float* W1    = (const float*)d_in[3];
    const float* b1    = (const float*)d_in[4];
    const float* W2    = (const float*)d_in[5];
    const float* b2    = (const float*)d_in[6];
    const float* W_ih  = (const float*)d_in[7];
    const float* b_ih  = (const float*)d_in[8];
    const float* W_hh  = (const float*)d_in[9];
    const float* b_hh  = (const float*)d_in[10];
    float* out = (float*)d_out;

    const int total = 32 * 256 + 64 * 128 + 32 * 384;
    repack_kernel<<<(total + 255) / 256, 256>>>(W1, W2, W_hh);
    ode_rnn_kernel<<<NCTAS, NTHREADS>>>(times, vals, mask,
                                        b1, b2, W_ih, b_ih, b_hh, out);
}

// round 7
// speedup vs baseline: 1.1120x; 1.1120x over previous
#include <cuda_runtime.h>

#define T_STEPS  1024
#define F_FEAT   2048
#define LATENT   128
#define ODE_H    256
#define GR       384          // 3*LATENT gate rows
#define G        16           // features per CTA
#define GP       8            // feature pairs per CTA
#define GPG      4            // feature pairs per group
#define NTHREADS 256
#define NCTAS    (F_FEAT / G) // 128

typedef unsigned long long u64;

// ---------- packed f32x2 helpers ----------
__device__ __forceinline__ u64 ffma2(u64 a, u64 b, u64 c) {
    u64 d;
    asm("fma.rn.f32x2 %0, %1, %2, %3;" : "=l"(d) : "l"(a), "l"(b), "l"(c));
    return d;
}
__device__ __forceinline__ u64 dup2(float x) {
    u64 r;
    asm("mov.b64 %0, {%1, %1};" : "=l"(r) : "f"(x));
    return r;
}
__device__ __forceinline__ float2 unpk(u64 v) {
    float2 r;
    asm("mov.b64 {%0, %1}, %2;" : "=f"(r.x), "=f"(r.y) : "l"(v));
    return r;
}
__device__ __forceinline__ u64 pack2(float x, float y) {
    u64 r;
    asm("mov.b64 %0, {%1, %2};" : "=l"(r) : "f"(x), "f"(y));
    return r;
}
// HW tanh (single MUFU op on sm_75+)
__device__ __forceinline__ float tanh_fast(float x) {
    float y;
    asm("tanh.approx.f32 %0, %1;" : "=f"(y) : "f"(x));
    return y;
}
__device__ __forceinline__ u64 tanh2(u64 v) {
    const float2 f = unpk(v);
    return pack2(tanh_fast(f.x), tanh_fast(f.y));
}
// sigmoid(x) = 0.5*tanh(0.5x) + 0.5  (1 MUFU + 2 FMA)
__device__ __forceinline__ float fast_sigmoid(float x) {
    return fmaf(0.5f, tanh_fast(0.5f * x), 0.5f);
}
#define GBAR(id) asm volatile("bar.sync %0, 128;" :: "r"(id) : "memory")

// ---------- repacked (transposed) weights: coalesced mainloop loads ----------
__device__ float4 g_W1p[32 * 256];   // [k4*256 + j] = W1[j][4k4..]
__device__ float4 g_W2p[64 * 128];   // [k4*128 + j] = W2[j][4k4..]
__device__ float4 g_Whp[32 * 384];   // [k4*384 + j] = W_hh[j][4k4..]

__global__ void repack_kernel(const float* __restrict__ W1,
                              const float* __restrict__ W2,
                              const float* __restrict__ Whh)
{
    int i = blockIdx.x * blockDim.x + threadIdx.x;
    if (i < 32 * 256) {
        int k4 = i >> 8, j = i & 255;
        g_W1p[k4 * 256 + j] = *(const float4*)(W1 + j * LATENT + 4 * k4);
    } else if (i < 32 * 256 + 64 * 128) {
        int t = i - 32 * 256;
        int k4 = t >> 7, j = t & 127;
        g_W2p[k4 * 128 + j] = *(const float4*)(W2 + j * ODE_H + 4 * k4);
    } else if (i < 32 * 256 + 64 * 128 + 32 * 384) {
        int t = i - (32 * 256 + 64 * 128);
        int k4 = t / 384, j = t % 384;
        g_Whp[k4 * 384 + j] = *(const float4*)(Whh + j * LATENT + 4 * k4);
    }
}

// ---------- main persistent recurrence kernel ----------
__global__ __launch_bounds__(NTHREADS, 1)
void ode_rnn_kernel(const float* __restrict__ times,
                    const float* __restrict__ vals,
                    const float* __restrict__ mask,
                    const float* __restrict__ b1,
                    const float* __restrict__ b2,
                    const float* __restrict__ W_ih,
                    const float* __restrict__ b_ih,
                    const float* __restrict__ b_hh,
                    float* __restrict__ out)
{
    // two independent groups; each owns 4 feature-pairs
    __shared__ __align__(16) u64 hp[GP * LATENT];    // 8 KB
    __shared__ __align__(16) u64 pool[GP * GR];      // 24 KB
    __shared__ float2 obs2[GP];
    __shared__ float2 m2[GP];

    const int tid = threadIdx.x;
    const int grp = tid >> 7;              // 0 or 1
    const int lt  = tid & 127;             // lane within group
    const int bar = grp + 1;               // named barrier id
    const int f0  = blockIdx.x * G;
    u64* __restrict__ hpg   = hp   + grp * GPG * LATENT;
    u64* __restrict__ poolg = pool + grp * GPG * GR;
    const int pb = grp * GPG;              // global pair base

    for (int idx = tid; idx < GP * LATENT; idx += NTHREADS)
        hp[idx] = 0ULL;
    __syncthreads();

    for (int i = 0; i < T_STEPS; ++i) {
        const int row = T_STEPS - 1 - i;               // reversed sequence
        float dt = 0.0f;
        if (i > 0) dt = __ldg(times + row + 1) - __ldg(times + row);

        if (lt < GPG) {
            obs2[pb + lt] = __ldg((const float2*)(vals + (long)row * F_FEAT + f0) + pb + lt);
            m2[pb + lt]   = __ldg((const float2*)(mask + (long)row * F_FEAT + f0) + pb + lt);
        }

        if (dt > 0.0f) {
            // ---- Phase 1: t1[p][j] = tanh(b1[j] + sum_k h2[p][k]*W1[j][k])
            //      JR=2 (rows lt, lt+128), 4 pairs ----
            {
                const int j0 = lt, j1 = lt + 128;
                u64 a0[GPG], a1[GPG];
                const u64 bj0 = dup2(__ldg(b1 + j0));
                const u64 bj1 = dup2(__ldg(b1 + j1));
                #pragma unroll
                for (int p = 0; p < GPG; ++p) { a0[p] = bj0; a1[p] = bj1; }
                #pragma unroll 4
                for (int k4 = 0; k4 < LATENT / 4; ++k4) {
                    const float4 wa = __ldg(g_W1p + k4 * ODE_H + j0);
                    const float4 wb = __ldg(g_W1p + k4 * ODE_H + j1);
                    const u64 wa0 = dup2(wa.x), wa1 = dup2(wa.y), wa2 = dup2(wa.z), wa3 = dup2(wa.w);
                    const u64 wb0 = dup2(wb.x), wb1 = dup2(wb.y), wb2 = dup2(wb.z), wb3 = dup2(wb.w);
                    #pragma unroll
                    for (int p = 0; p < GPG; ++p) {
                        const ulonglong2* hv = (const ulonglong2*)(hpg + p * LATENT);
                        const ulonglong2 x = hv[2 * k4];
                        const ulonglong2 y = hv[2 * k4 + 1];
                        a0[p] = ffma2(x.x, wa0, a0[p]); a1[p] = ffma2(x.x, wb0, a1[p]);
                        a0[p] = ffma2(x.y, wa1, a0[p]); a1[p] = ffma2(x.y, wb1, a1[p]);
                        a0[p] = ffma2(y.x, wa2, a0[p]); a1[p] = ffma2(y.x, wb2, a1[p]);
                        a0[p] = ffma2(y.y, wa3, a0[p]); a1[p] = ffma2(y.y, wb3, a1[p]);
                    }
                }
                #pragma unroll
                for (int p = 0; p < GPG; ++p) {
                    poolg[p * ODE_H + j0] = tanh2(a0[p]);
                    poolg[p * ODE_H + j1] = tanh2(a1[p]);
                }
            }
            GBAR(bar);

            // ---- Phase 2: h2[p][j] += dt * (b2[j] + sum_k t1[p][k]*W2[j][k])
            //      JR=1 (row lt), 4 pairs ----
            {
                const int j = lt;
                u64 acc[GPG];
                const u64 bj = dup2(__ldg(b2 + j));
                #pragma unroll
                for (int p = 0; p < GPG; ++p) acc[p] = bj;
                #pragma unroll 4
                for (int k4 = 0; k4 < ODE_H / 4; ++k4) {
                    const float4 w = __ldg(g_W2p + k4 * LATENT + j);
                    const u64 w0 = dup2(w.x), w1 = dup2(w.y), w2 = dup2(w.z), w3 = dup2(w.w);
                    #pragma unroll
                    for (int p = 0; p < GPG; ++p) {
                        const ulonglong2* tv = (const ulonglong2*)(poolg + p * ODE_H);
                        const ulonglong2 x = tv[2 * k4];
                        const ulonglong2 y = tv[2 * k4 + 1];
                        acc[p] = ffma2(x.x, w0, acc[p]);
                        acc[p] = ffma2(x.y, w1, acc[p]);
                        acc[p] = ffma2(y.x, w2, acc[p]);
                        acc[p] = ffma2(y.y, w3, acc[p]);
                    }
                }
                const u64 dt2 = dup2(dt);
                #pragma unroll
                for (int p = 0; p < GPG; ++p)
                    hpg[p * LATENT + j] = ffma2(acc[p], dt2, hpg[p * LATENT + j]);
            }
            GBAR(bar);
        }

        // ---- Phase 3: gh[p][j] = b_hh[j] + sum_k h2[p][k]*W_hh[j][k]
        //      JR=3 (rows lt, lt+128, lt+256), 4 pairs ----
        {
            const int j0 = lt, j1 = lt + 128, j2 = lt + 256;
            u64 a0[GPG], a1[GPG], a2[GPG];
            const u64 bj0 = dup2(__ldg(b_hh + j0));
            const u64 bj1 = dup2(__ldg(b_hh + j1));
            const u64 bj2 = dup2(__ldg(b_hh + j2));
            #pragma unroll
            for (int p = 0; p < GPG; ++p) { a0[p] = bj0; a1[p] = bj1; a2[p] = bj2; }
            #pragma unroll 4
            for (int k4 = 0; k4 < LATENT / 4; ++k4) {
                const float4 wa = __ldg(g_Whp + k4 * GR + j0);
                const float4 wb = __ldg(g_Whp + k4 * GR + j1);
                const float4 wc = __ldg(g_Whp + k4 * GR + j2);
                const u64 wa0 = dup2(wa.x), wa1 = dup2(wa.y), wa2 = dup2(wa.z), wa3 = dup2(wa.w);
                const u64 wb0 = dup2(wb.x), wb1 = dup2(wb.y), wb2 = dup2(wb.z), wb3 = dup2(wb.w);
                const u64 wc0 = dup2(wc.x), wc1 = dup2(wc.y), wc2 = dup2(wc.z), wc3 = dup2(wc.w);
                #pragma unroll
                for (int p = 0; p < GPG; ++p) {
                    const ulonglong2* hv = (const ulonglong2*)(hpg + p * LATENT);
                    const ulonglong2 x = hv[2 * k4];
                    const ulonglong2 y = hv[2 * k4 + 1];
                    a0[p] = ffma2(x.x, wa0, a0[p]); a1[p] = ffma2(x.x, wb0, a1[p]); a2[p] = ffma2(x.x, wc0, a2[p]);
                    a0[p] = ffma2(x.y, wa1, a0[p]); a1[p] = ffma2(x.y, wb1, a1[p]); a2[p] = ffma2(x.y, wc1, a2[p]);
                    a0[p] = ffma2(y.x, wa2, a0[p]); a1[p] = ffma2(y.x, wb2, a1[p]); a2[p] = ffma2(y.x, wc2, a2[p]);
                    a0[p] = ffma2(y.y, wa3, a0[p]); a1[p] = ffma2(y.y, wb3, a1[p]); a2[p] = ffma2(y.y, wc3, a2[p]);
                }
            }
            #pragma unroll
            for (int p = 0; p < GPG; ++p) {
                poolg[p * GR + j0] = a0[p];
                poolg[p * GR + j1] = a1[p];
                poolg[p * GR + j2] = a2[p];
            }
        }
        GBAR(bar);

        // ---- Update: GRU gates + mask mix (512 pair-elems per group) ----
        #pragma unroll
        for (int rep = 0; rep < (GPG * LATENT) / 128; ++rep) {
            const int idx = rep * 128 + lt;
            const int p = idx >> 7;               // local pair 0..3
            const int l = idx & (LATENT - 1);
            const float2 gr = unpk(poolg[p * GR + l]);
            const float2 gz = unpk(poolg[p * GR + LATENT + l]);
            const float2 gn = unpk(poolg[p * GR + 2 * LATENT + l]);
            const float2 ob = obs2[pb + p];
            const float2 mm = m2[pb + p];
            const float2 h  = unpk(hpg[p * LATENT + l]);
            const float wr = __ldg(W_ih + l);
            const float wz = __ldg(W_ih + LATENT + l);
            const float wn = __ldg(W_ih + 2 * LATENT + l);
            const float br = __ldg(b_ih + l);
            const float bz = __ldg(b_ih + LATENT + l);
            const float bn = __ldg(b_ih + 2 * LATENT + l);

            const float rX = fast_sigmoid(fmaf(ob.x, wr, br) + gr.x);
            const float zX = fast_sigmoid(fmaf(ob.x, wz, bz) + gz.x);
            const float nX = tanh_fast(fmaf(ob.x, wn, bn) + rX * gn.x);
            const float hcX = fmaf(zX, h.x - nX, nX);
            const float hX  = fmaf(mm.x, hcX - h.x, h.x);

            const float rY = fast_sigmoid(fmaf(ob.y, wr, br) + gr.y);
            const float zY = fast_sigmoid(fmaf(ob.y, wz, bz) + gz.y);
            const float nY = tanh_fast(fmaf(ob.y, wn, bn) + rY * gn.y);
            const float hcY = fmaf(zY, h.y - nY, nY);
            const float hY  = fmaf(mm.y, hcY - h.y, h.y);

            hpg[p * LATENT + l] = pack2(hX, hY);
        }
        GBAR(bar);
    }

    // write final h for this group's 4 pairs
    #pragma unroll
    for (int rep = 0; rep < (GPG * LATENT) / 128; ++rep) {
        const int idx = rep * 128 + lt;
        const int p = idx >> 7;
        const int l = idx & (LATENT - 1);
        const float2 v = unpk(hpg[p * LATENT + l]);
        out[(long)(f0 + 2 * (pb + p))     * LATENT + l] = v.x;
        out[(long)(f0 + 2 * (pb + p) + 1) * LATENT + l] = v.y;
    }
}

extern "C" void kernel_launch(void* const* d_in, const int* in_sizes, int n_in,
                              void* d_out, int out_size)
{
    (void)in_sizes; (void)n_in; (void)out_size;
    const float* times = (const float*)d_in[0];
    const float* vals  = (const float*)d_in[1];
    const float* mask  = (const float*)d_in[2];
    const float* W1    = (const float*)d_in[3];
    const float* b1    = (const float*)d_in[4];
    const float* W2    = (const float*)d_in[5];
    const float* b2    = (const float*)d_in[6];
    const float* W_ih  = (const float*)d_in[7];
    const float* b_ih  = (const float*)d_in[8];
    const float* W_hh  = (const float*)d_in[9];
    const float* b_hh  = (const float*)d_in[10];
    float* out = (float*)d_out;

    const int total = 32 * 256 + 64 * 128 + 32 * 384;
    repack_kernel<<<(total + 255) / 256, 256>>>(W1, W2, W_hh);
    ode_rnn_kernel<<<NCTAS, NTHREADS>>>(times, vals, mask,
                                        b1, b2, W_ih, b_ih, b_hh, out);
}